// round 15
// baseline (speedup 1.0000x reference)
#include <cuda_runtime.h>
#include <cuda_bf16.h>
#include <cuda_fp16.h>
#include <math.h>

#define BB   64
#define TT   1024
#define CC   512
#define HH   512
#define G4   2048
#define PADK 40   // padded k-stride for mm_kernel smem tiles
#define SPAD 520  // padded k-stride for scan smem tiles

// ---------------- scratch (static device memory; no allocs) ----------------
__device__ __half g_Axn[(size_t)TT * BB * CC];         // LN(x) fp16, time-major [t*B+b][C]
__device__ __half g_Bp[4096 * 512];                    // stacked Wih_f | Wih_b fp16
__device__ float g_xg_f[(size_t)TT * BB * G4];         // input projection fwd (fp32)
__device__ float g_xg_b[(size_t)TT * BB * G4];
__device__ __half g_AcatH[(size_t)BB * TT * 2 * HH];   // concat(fw,bw) fp16 [b*T+t][2H]
__device__ __half g_Bg[512 * 1024];                    // Wg fp16
__device__ float g_Hout[(size_t)BB * TT * HH];

// ---------------- fast math ----------------
__device__ __forceinline__ float ex2f(float x) { float r; asm("ex2.approx.f32 %0, %1;" : "=f"(r) : "f"(x)); return r; }
__device__ __forceinline__ float rcpf(float x) { float r; asm("rcp.approx.f32 %0, %1;" : "=f"(r) : "f"(x)); return r; }
__device__ __forceinline__ float fsig(float x) { return rcpf(1.f + ex2f(-1.4426950408889634f * x)); }
__device__ __forceinline__ float ftanh(float x) { return 1.f - 2.f * rcpf(1.f + ex2f(2.8853900817779268f * x)); }

// ---------------- mma / ldmatrix / cluster helpers ----------------
__device__ __forceinline__ void mma_f16(float* d, const unsigned* a, const unsigned* b) {
    asm volatile(
        "mma.sync.aligned.m16n8k16.row.col.f32.f16.f16.f32 "
        "{%0,%1,%2,%3}, {%4,%5,%6,%7}, {%8,%9}, {%0,%1,%2,%3};"
        : "+f"(d[0]), "+f"(d[1]), "+f"(d[2]), "+f"(d[3])
        : "r"(a[0]), "r"(a[1]), "r"(a[2]), "r"(a[3]), "r"(b[0]), "r"(b[1]));
}

#define LDSMX4(R, ADDR) \
    asm volatile("ldmatrix.sync.aligned.m8n8.x4.shared.b16 {%0,%1,%2,%3}, [%4];" \
                 : "=r"((R)[0]), "=r"((R)[1]), "=r"((R)[2]), "=r"((R)[3]) : "r"(ADDR))

#define MAPA(DST, ADDR, RANK) \
    asm volatile("mapa.shared::cluster.u32 %0, %1, %2;" : "=r"(DST) : "r"(ADDR), "r"(RANK))
#define STSC32(ADDR, VAL) \
    asm volatile("st.shared::cluster.b32 [%0], %1;" :: "r"(ADDR), "r"(VAL) : "memory")
#define CLUSTER_ARRIVE() asm volatile("barrier.cluster.arrive.aligned;" ::: "memory")
#define CLUSTER_WAIT()   asm volatile("barrier.cluster.wait.aligned;" ::: "memory")

__device__ __forceinline__ unsigned s2u(const void* p) {
    unsigned r;
    asm("{ .reg .u64 t; cvta.to.shared.u64 t, %1; cvt.u32.u64 %0, t; }" : "=r"(r) : "l"(p));
    return r;
}

// ---------------- block reduce ----------------
__device__ __forceinline__ float block_reduce(float v, float* red) {
    int lane = threadIdx.x & 31, wid = threadIdx.x >> 5;
#pragma unroll
    for (int o = 16; o > 0; o >>= 1) v += __shfl_xor_sync(0xffffffffu, v, o);
    if (lane == 0) red[wid] = v;
    __syncthreads();
    if (wid == 0) {
        float w = (lane < 8) ? red[lane] : 0.f;
#pragma unroll
        for (int o = 4; o > 0; o >>= 1) w += __shfl_xor_sync(0xffffffffu, w, o);
        if (lane == 0) red[8] = w;
    }
    __syncthreads();
    float r = red[8];
    __syncthreads();
    return r;
}

// ---------------- kernel 1: layernorm(x) -> fp16 (time-major) ----------------
__global__ void ln_x_kernel(const float* __restrict__ x,
                            const float* __restrict__ gx,
                            const float* __restrict__ bx) {
    __shared__ float red[9];
    int r = blockIdx.x;
    int b = r >> 10, t = r & 1023;
    const float* row = x + (size_t)r * CC;
    int c0 = threadIdx.x, c1 = threadIdx.x + 256;
    float v0 = row[c0], v1 = row[c1];
    float mean = block_reduce(v0 + v1, red) * (1.f / CC);
    float d0 = v0 - mean, d1 = v1 - mean;
    float var = block_reduce(d0 * d0 + d1 * d1, red) * (1.f / CC);
    float rstd = rsqrtf(var + 1e-5f);
    size_t base = ((size_t)t * BB + b) * CC;
    g_Axn[base + c0] = __float2half(d0 * rstd * gx[c0] + bx[c0]);
    g_Axn[base + c1] = __float2half(d1 * rstd * gx[c1] + bx[c1]);
}

// ---------------- weight conversion ----------------
__global__ void convW_proj(const float* __restrict__ Wf, const float* __restrict__ Wb) {
    int n = blockIdx.x;
    const float* src = (n < 2048) ? (Wf + (size_t)n * 512) : (Wb + (size_t)(n - 2048) * 512);
    size_t base = (size_t)n * 512;
    for (int k = threadIdx.x; k < 512; k += 256) g_Bp[base + k] = __float2half(src[k]);
}
__global__ void convW_gate(const float* __restrict__ Wg) {
    int n = blockIdx.x;
    size_t base = (size_t)n * 1024;
    for (int k = threadIdx.x; k < 1024; k += 256) g_Bg[base + k] = __float2half(Wg[base + k]);
}

// ---------------- HMMA GEMM fp16 single-pass: D = A . B^T ----------
template <int KDIM, int EPI>
__global__ void __launch_bounds__(256, 1) mm_kernel(const float* __restrict__ bias0,
                                                    const float* __restrict__ bias1) {
    __shared__ __half sA[128 * PADK];
    __shared__ __half sB[128 * PADK];

    const int tid = threadIdx.x;
    const int warp = tid >> 5, lane = tid & 31;
    const int g = lane >> 2, q = lane & 3;
    const int wm = (warp >> 1) * 32;
    const int wn = (warp & 1) * 64;
    const int m0 = blockIdx.y * 128;
    const int n0 = blockIdx.x * 128;

    const __half* A = (EPI == 0) ? g_Axn : g_AcatH;
    const __half* B = (EPI == 0) ? g_Bp : g_Bg;

    const int r0 = tid >> 2, kq0 = (tid & 3) * 8;
    const int r1 = r0 + 64;
    const __half* pA0 = A + (size_t)(m0 + r0) * KDIM + kq0;
    const __half* pA1 = A + (size_t)(m0 + r1) * KDIM + kq0;
    const __half* pB0 = B + (size_t)(n0 + r0) * KDIM + kq0;
    const __half* pB1 = B + (size_t)(n0 + r1) * KDIM + kq0;

    const int lrow = (lane & 7) + 8 * ((lane >> 3) & 1);
    const int lcol = 8 * (lane >> 4);
    const unsigned uA = s2u(sA), uB = s2u(sB);
    const unsigned offA0 = (unsigned)(((wm + lrow) * PADK + lcol) * 2);
    const unsigned offA1 = offA0 + 16 * PADK * 2;
    const unsigned offB  = (unsigned)(((wn + lrow) * PADK + lcol) * 2);

    float acc[2][8][4];
#pragma unroll
    for (int i = 0; i < 2; ++i)
#pragma unroll
        for (int j = 0; j < 8; ++j)
#pragma unroll
            for (int v = 0; v < 4; ++v) acc[i][j][v] = 0.f;

    uint4 vA0 = *(const uint4*)pA0, vA1 = *(const uint4*)pA1;
    uint4 vB0 = *(const uint4*)pB0, vB1 = *(const uint4*)pB1;

    const int NCH = KDIM / 32;
    for (int c = 0; c < NCH; ++c) {
        *(uint4*)&sA[r0 * PADK + kq0] = vA0;  *(uint4*)&sA[r1 * PADK + kq0] = vA1;
        *(uint4*)&sB[r0 * PADK + kq0] = vB0;  *(uint4*)&sB[r1 * PADK + kq0] = vB1;
        __syncthreads();

        if (c + 1 < NCH) {
            int koff = (c + 1) * 32;
            vA0 = *(const uint4*)(pA0 + koff);  vA1 = *(const uint4*)(pA1 + koff);
            vB0 = *(const uint4*)(pB0 + koff);  vB1 = *(const uint4*)(pB1 + koff);
        }

#pragma unroll
        for (int ks = 0; ks < 32; ks += 16) {
            unsigned a0[4], a1[4];
            LDSMX4(a0, uA + offA0 + ks * 2);
            LDSMX4(a1, uA + offA1 + ks * 2);
#pragma unroll
            for (int p = 0; p < 4; ++p) {
                unsigned b4[4];
                LDSMX4(b4, uB + offB + (p * 16 * PADK + ks) * 2);
#pragma unroll
                for (int e = 0; e < 2; ++e) {
                    unsigned b2[2] = {b4[e], b4[2 + e]};
                    int nt = 2 * p + e;
                    mma_f16(acc[0][nt], a0, b2);
                    mma_f16(acc[1][nt], a1, b2);
                }
            }
        }
        __syncthreads();
    }

    if (EPI == 0) {
        const bool isf = (n0 < 2048);
        float* Y = isf ? g_xg_f : g_xg_b;
        const float* bias = isf ? bias0 : bias1;
        const int nb = (n0 & 2047) + wn;
#pragma unroll
        for (int mt = 0; mt < 2; ++mt) {
            int mrow = m0 + wm + mt * 16 + g;
#pragma unroll
            for (int nt = 0; nt < 8; ++nt) {
                int ncol = nb + nt * 8 + 2 * q;
                float bx0 = bias[ncol], bx1 = bias[ncol + 1];
                float2 v0 = make_float2(acc[mt][nt][0] + bx0, acc[mt][nt][1] + bx1);
                float2 v1 = make_float2(acc[mt][nt][2] + bx0, acc[mt][nt][3] + bx1);
                *(float2*)(Y + (size_t)mrow * 2048 + ncol) = v0;
                *(float2*)(Y + (size_t)(mrow + 8) * 2048 + ncol) = v1;
            }
        }
    } else {
#pragma unroll
        for (int mt = 0; mt < 2; ++mt) {
            int mrow = m0 + wm + mt * 16 + g;
#pragma unroll
            for (int nt = 0; nt < 8; ++nt) {
                int ncol = n0 + wn + nt * 8 + 2 * q;
                float bx0 = bias0[ncol], bx1 = bias0[ncol + 1];
#pragma unroll
                for (int hh = 0; hh < 2; ++hh) {
                    int m = mrow + hh * 8;
                    float s0 = fsig(acc[mt][nt][2 * hh + 0] + bx0);
                    float s1 = fsig(acc[mt][nt][2 * hh + 1] + bx1);
                    size_t ab = (size_t)m * 1024 + ncol;
                    float2 fw = __half22float2(*(const __half2*)(g_AcatH + ab));
                    float2 bw = __half22float2(*(const __half2*)(g_AcatH + ab + 512));
                    float2 o;
                    o.x = s0 * fw.x + (1.f - s0) * bw.x;
                    o.y = s1 * fw.y + (1.f - s1) * bw.y;
                    *(float2*)(g_Hout + (size_t)m * 512 + ncol) = o;
                }
            }
        }
    }
}

// ---------------- persistent bidirectional LSTM scan (fp16 HMMA, DSMEM cluster) ----
// 128 CTAs = 8 clusters of 16. Cluster = (dir, batch-group of 16); rank = unit slice
// (32 units = 128 gate cols). h exchange via st.shared::cluster into peers' smem,
// double-buffered by step parity; one barrier.cluster per step.
__global__ void __launch_bounds__(256, 1) scan_kernel(
    const float* __restrict__ Whh_f, const float* __restrict__ bhh_f,
    const float* __restrict__ Whh_b, const float* __restrict__ bhh_b) {
    extern __shared__ char smc[];
    __half* sB = (__half*)smc;                 // [128][SPAD] Whh fp16 (static)
    __half* sH = sB + 128 * SPAD;              // [2][16][SPAD] h (parity buffers)
    float* sG   = (float*)(sH + 2 * 16 * SPAD); // [16][130]
    float* sC   = sG + 16 * 130;               // [512]
    float* sBhh = sC + 512;                    // [128]

    const int tid  = threadIdx.x;
    const int warp = tid >> 5, lane = tid & 31;
    const int g = lane >> 2, q = lane & 3;
    const int dir = blockIdx.x >> 6;
    const int grp = (blockIdx.x >> 4) & 3;
    const int j0  = (blockIdx.x & 15) * 32;    // this CTA's 32 units
    const int b0g = grp * 16;                  // batch offset
    const int wn  = warp * 16;                 // gate-col offset (8 warps x 16 = 128)

    const float* Whh = dir ? Whh_b : Whh_f;
    const float* bhh = dir ? bhh_b : bhh_f;
    const float* xg  = dir ? g_xg_b : g_xg_f;

    const unsigned uB = s2u(sB);
    const unsigned uH = s2u(sH);
    const unsigned PSTRIDE = 16 * SPAD * 2;    // parity buffer stride (bytes)

    // ---- load Whh slice [128 cols][512] fp16 ----
    {
        int row = tid >> 1;
        int k0 = (tid & 1) * 256;
        int ngl = (row >> 5) * 512 + j0 + (row & 31);
        const float* src = Whh + (size_t)ngl * 512 + k0;
#pragma unroll
        for (int k4 = 0; k4 < 256; k4 += 4) {
            float4 v = *(const float4*)(src + k4);
            sB[row * SPAD + k0 + k4 + 0] = __float2half(v.x);
            sB[row * SPAD + k0 + k4 + 1] = __float2half(v.y);
            sB[row * SPAD + k0 + k4 + 2] = __float2half(v.z);
            sB[row * SPAD + k0 + k4 + 3] = __float2half(v.w);
        }
    }
    if (tid < 128) sBhh[tid] = bhh[(tid >> 5) * 512 + j0 + (tid & 31)];
    for (int idx = tid; idx < 512; idx += 256) sC[idx] = 0.f;
    // zero parity-0 h buffer (full 16x512)
    {
        __half2 z2 = __floats2half2_rn(0.f, 0.f);
        for (int i = tid; i < 4096; i += 256) {
            int row = i >> 8, c2 = (i & 255) * 2;
            *(__half2*)&sH[row * SPAD + c2] = z2;
        }
    }
    __syncthreads();
    CLUSTER_ARRIVE();
    CLUSTER_WAIT();

    // fragment addressing (static)
    const int lrow = (lane & 7) + 8 * ((lane >> 3) & 1);
    const int lcol = 8 * (lane >> 4);
    const unsigned aA0 = uH + (unsigned)((lrow * SPAD + lcol) * 2);
    const unsigned aB  = uB + (unsigned)(((wn + lrow) * SPAD + lcol) * 2);

    // epilogue indices (static)
    const int c0a = wn + 2 * q;
    const int c0b = wn + 8 + 2 * q;
    const int ngba = (c0a >> 5) * 512 + j0 + (c0a & 31);
    const int ngbb = (c0b >> 5) * 512 + j0 + (c0b & 31);
    const int r0 = g, r1 = g + 8;
    const float2 bb0 = *(const float2*)&sBhh[c0a];
    const float2 bb1 = *(const float2*)&sBhh[c0b];

    // activation indices (static): this thread produces h for (batch ab2, units j0+au2, +1)
    const int ab2 = (tid * 2) >> 5, au2 = (tid * 2) & 31;

    // precompute remote addresses of this thread's h slot in every peer CTA (parity 0)
    unsigned rem[16];
    {
        unsigned slot0 = uH + (unsigned)((ab2 * SPAD + j0 + au2) * 2);
#pragma unroll
        for (int r = 0; r < 16; ++r) MAPA(rem[r], slot0, r);
    }

    for (int s = 0; s < TT; ++s) {
        const int t = dir ? (TT - 1 - s) : s;
        const unsigned pofs  = (unsigned)(s & 1) * PSTRIDE;       // read buffer
        const unsigned pofsN = (unsigned)((s + 1) & 1) * PSTRIDE; // write buffer

        // ---- xg prefetch (DRAM; consumed in epilogue) ----
        const float* xgt = xg + (size_t)t * BB * G4;
        float2 xv00 = __ldcg((const float2*)(xgt + (size_t)(b0g + r0) * G4 + ngba));
        float2 xv01 = __ldcg((const float2*)(xgt + (size_t)(b0g + r1) * G4 + ngba));
        float2 xv10 = __ldcg((const float2*)(xgt + (size_t)(b0g + r0) * G4 + ngbb));
        float2 xv11 = __ldcg((const float2*)(xgt + (size_t)(b0g + r1) * G4 + ngbb));

        // ---- MMA: gates[16,128] = h[16,512] . Whh_slice[128,512]^T ----
        float acc[2][4];
#pragma unroll
        for (int nt = 0; nt < 2; ++nt)
#pragma unroll
            for (int v = 0; v < 4; ++v) acc[nt][v] = 0.f;

        const unsigned aA = aA0 + pofs;
#pragma unroll
        for (int ks = 0; ks < 512; ks += 16) {
            unsigned a4[4], b4[4];
            LDSMX4(a4, aA + (unsigned)(ks * 2));
            LDSMX4(b4, aB + (unsigned)(ks * 2));
#pragma unroll
            for (int e = 0; e < 2; ++e) {
                unsigned b2[2] = {b4[e], b4[2 + e]};
                mma_f16(acc[e], a4, b2);
            }
        }

        // ---- epilogue: add xg + bhh, write gates to smem ----
        *(float2*)&sG[r0 * 130 + c0a] =
            make_float2(acc[0][0] + xv00.x + bb0.x, acc[0][1] + xv00.y + bb0.y);
        *(float2*)&sG[r1 * 130 + c0a] =
            make_float2(acc[0][2] + xv01.x + bb0.x, acc[0][3] + xv01.y + bb0.y);
        *(float2*)&sG[r0 * 130 + c0b] =
            make_float2(acc[1][0] + xv10.x + bb1.x, acc[1][1] + xv10.y + bb1.y);
        *(float2*)&sG[r1 * 130 + c0b] =
            make_float2(acc[1][2] + xv11.x + bb1.x, acc[1][3] + xv11.y + bb1.y);
        __syncthreads();

        // ---- activation + broadcast h to all cluster CTAs' sH[parity^1] ----
        {
            float2 gi = *(const float2*)&sG[ab2 * 130 + au2];
            float2 gf = *(const float2*)&sG[ab2 * 130 + 32 + au2];
            float2 gg = *(const float2*)&sG[ab2 * 130 + 64 + au2];
            float2 go = *(const float2*)&sG[ab2 * 130 + 96 + au2];
            float2 cold = *(const float2*)&sC[tid * 2];
            float cn0 = fsig(gf.x) * cold.x + fsig(gi.x) * ftanh(gg.x);
            float cn1 = fsig(gf.y) * cold.y + fsig(gi.y) * ftanh(gg.y);
            float hn0 = fsig(go.x) * ftanh(cn0);
            float hn1 = fsig(go.y) * ftanh(cn1);
            *(float2*)&sC[tid * 2] = make_float2(cn0, cn1);
            __half2 h2 = __floats2half2_rn(hn0, hn1);
            unsigned hv = *(unsigned*)&h2;
#pragma unroll
            for (int r = 0; r < 16; ++r) STSC32(rem[r] + pofsN, hv);
            int bg2 = b0g + ab2;
            size_t ar = ((size_t)bg2 * TT + t) * 1024 + (size_t)dir * 512 + j0 + au2;
            *(__half2*)&g_AcatH[ar] = h2;
        }
        // one cluster barrier per step: orders DSMEM h writes, acts as block sync too
        CLUSTER_ARRIVE();
        CLUSTER_WAIT();
    }
}

// ---------------- final layernorm -> d_out ----------------
__global__ void ln_out_kernel(const float* __restrict__ gH,
                              const float* __restrict__ bH,
                              float* __restrict__ out) {
    __shared__ float red[9];
    int r = blockIdx.x;
    const float* row = g_Hout + (size_t)r * HH;
    int c0 = threadIdx.x, c1 = threadIdx.x + 256;
    float v0 = row[c0], v1 = row[c1];
    float mean = block_reduce(v0 + v1, red) * (1.f / HH);
    float d0 = v0 - mean, d1 = v1 - mean;
    float var = block_reduce(d0 * d0 + d1 * d1, red) * (1.f / HH);
    float rstd = rsqrtf(var + 1e-5f);
    out[(size_t)r * HH + c0] = d0 * rstd * gH[c0] + bH[c0];
    out[(size_t)r * HH + c1] = d1 * rstd * gH[c1] + bH[c1];
}

// ---------------- launch ----------------
extern "C" void kernel_launch(void* const* d_in, const int* in_sizes, int n_in,
                              void* d_out, int out_size) {
    const float* x     = (const float*)d_in[0];
    const float* Wih_f = (const float*)d_in[2];
    const float* Whh_f = (const float*)d_in[3];
    const float* bih_f = (const float*)d_in[4];
    const float* bhh_f = (const float*)d_in[5];
    const float* Wih_b = (const float*)d_in[6];
    const float* Whh_b = (const float*)d_in[7];
    const float* bih_b = (const float*)d_in[8];
    const float* bhh_b = (const float*)d_in[9];
    const float* Wg    = (const float*)d_in[10];
    const float* bg    = (const float*)d_in[11];
    const float* gx    = (const float*)d_in[12];
    const float* bx    = (const float*)d_in[13];
    const float* gH    = (const float*)d_in[14];
    const float* bH    = (const float*)d_in[15];
    float* out = (float*)d_out;

    const int scan_smem = (128 * SPAD + 2 * 16 * SPAD) * 2   /* fp16 tiles */
                        + (16 * 130 + 512 + 128) * 4;        /* fp32 */
    cudaFuncSetAttribute(scan_kernel, cudaFuncAttributeMaxDynamicSharedMemorySize, scan_smem);
    cudaFuncSetAttribute(scan_kernel, cudaFuncAttributeNonPortableClusterSizeAllowed, 1);

    ln_x_kernel<<<BB * TT, 256>>>(x, gx, bx);
    convW_proj<<<4096, 256>>>(Wih_f, Wih_b);
    convW_gate<<<512, 256>>>(Wg);
    mm_kernel<512, 0><<<dim3(4096 / 128, (BB * TT) / 128), 256>>>(bih_f, bih_b);

    // cluster launch: 8 clusters x 16 CTAs
    {
        cudaLaunchConfig_t cfg = {};
        cfg.gridDim = dim3(128, 1, 1);
        cfg.blockDim = dim3(256, 1, 1);
        cfg.dynamicSmemBytes = (size_t)scan_smem;
        cfg.stream = 0;
        cudaLaunchAttribute attrs[1];
        attrs[0].id = cudaLaunchAttributeClusterDimension;
        attrs[0].val.clusterDim.x = 16;
        attrs[0].val.clusterDim.y = 1;
        attrs[0].val.clusterDim.z = 1;
        cfg.attrs = attrs;
        cfg.numAttrs = 1;
        cudaLaunchKernelEx(&cfg, scan_kernel, Whh_f, bhh_f, Whh_b, bhh_b);
    }

    mm_kernel<1024, 1><<<dim3(512 / 128, (BB * TT) / 128), 256>>>(bg, bg);
    ln_out_kernel<<<BB * TT, 256>>>(gH, bH, out);
}

// round 16
// speedup vs baseline: 1.0011x; 1.0011x over previous
#include <cuda_runtime.h>
#include <cuda_bf16.h>
#include <cuda_fp16.h>
#include <math.h>

#define BB   64
#define TT   1024
#define CC   512
#define HH   512
#define G4   2048
#define PADK 40   // padded k-stride for mm_kernel smem tiles
#define SPAD 520  // padded k-stride for scan smem tiles

// ---------------- scratch (static device memory; no allocs) ----------------
__device__ __half g_Axn[(size_t)TT * BB * CC];         // LN(x) fp16, time-major [t*B+b][C]
__device__ __half g_Bp[4096 * 512];                    // stacked Wih_f | Wih_b fp16
__device__ float g_xg_f[(size_t)TT * BB * G4];         // input projection fwd (fp32)
__device__ float g_xg_b[(size_t)TT * BB * G4];
__device__ __half g_AcatH[(size_t)BB * TT * 2 * HH];   // concat(fw,bw) fp16 [b*T+t][2H]
__device__ __half g_Bg[512 * 1024];                    // Wg fp16
__device__ float g_Hout[(size_t)BB * TT * HH];

// ---------------- fast math ----------------
__device__ __forceinline__ float ex2f(float x) { float r; asm("ex2.approx.f32 %0, %1;" : "=f"(r) : "f"(x)); return r; }
__device__ __forceinline__ float rcpf(float x) { float r; asm("rcp.approx.f32 %0, %1;" : "=f"(r) : "f"(x)); return r; }
__device__ __forceinline__ float fsig(float x) { return rcpf(1.f + ex2f(-1.4426950408889634f * x)); }
__device__ __forceinline__ float ftanh(float x) { return 1.f - 2.f * rcpf(1.f + ex2f(2.8853900817779268f * x)); }

// ---------------- mma / ldmatrix / cluster helpers ----------------
__device__ __forceinline__ void mma_f16(float* d, const unsigned* a, const unsigned* b) {
    asm volatile(
        "mma.sync.aligned.m16n8k16.row.col.f32.f16.f16.f32 "
        "{%0,%1,%2,%3}, {%4,%5,%6,%7}, {%8,%9}, {%0,%1,%2,%3};"
        : "+f"(d[0]), "+f"(d[1]), "+f"(d[2]), "+f"(d[3])
        : "r"(a[0]), "r"(a[1]), "r"(a[2]), "r"(a[3]), "r"(b[0]), "r"(b[1]));
}

#define LDSMX4(R, ADDR) \
    asm volatile("ldmatrix.sync.aligned.m8n8.x4.shared.b16 {%0,%1,%2,%3}, [%4];" \
                 : "=r"((R)[0]), "=r"((R)[1]), "=r"((R)[2]), "=r"((R)[3]) : "r"(ADDR))

#define MAPA(DST, ADDR, RANK) \
    asm volatile("mapa.shared::cluster.u32 %0, %1, %2;" : "=r"(DST) : "r"(ADDR), "r"(RANK))
#define STSC32(ADDR, VAL) \
    asm volatile("st.shared::cluster.b32 [%0], %1;" :: "r"(ADDR), "r"(VAL) : "memory")
#define CLUSTER_ARRIVE() asm volatile("barrier.cluster.arrive.aligned;" ::: "memory")
#define CLUSTER_WAIT()   asm volatile("barrier.cluster.wait.aligned;" ::: "memory")

__device__ __forceinline__ unsigned s2u(const void* p) {
    unsigned r;
    asm("{ .reg .u64 t; cvta.to.shared.u64 t, %1; cvt.u32.u64 %0, t; }" : "=r"(r) : "l"(p));
    return r;
}

// ---------------- block reduce ----------------
__device__ __forceinline__ float block_reduce(float v, float* red) {
    int lane = threadIdx.x & 31, wid = threadIdx.x >> 5;
#pragma unroll
    for (int o = 16; o > 0; o >>= 1) v += __shfl_xor_sync(0xffffffffu, v, o);
    if (lane == 0) red[wid] = v;
    __syncthreads();
    if (wid == 0) {
        float w = (lane < 8) ? red[lane] : 0.f;
#pragma unroll
        for (int o = 4; o > 0; o >>= 1) w += __shfl_xor_sync(0xffffffffu, w, o);
        if (lane == 0) red[8] = w;
    }
    __syncthreads();
    float r = red[8];
    __syncthreads();
    return r;
}

// ---------------- kernel 1: layernorm(x) -> fp16 (time-major) ----------------
__global__ void ln_x_kernel(const float* __restrict__ x,
                            const float* __restrict__ gx,
                            const float* __restrict__ bx) {
    __shared__ float red[9];
    int r = blockIdx.x;
    int b = r >> 10, t = r & 1023;
    const float* row = x + (size_t)r * CC;
    int c0 = threadIdx.x, c1 = threadIdx.x + 256;
    float v0 = row[c0], v1 = row[c1];
    float mean = block_reduce(v0 + v1, red) * (1.f / CC);
    float d0 = v0 - mean, d1 = v1 - mean;
    float var = block_reduce(d0 * d0 + d1 * d1, red) * (1.f / CC);
    float rstd = rsqrtf(var + 1e-5f);
    size_t base = ((size_t)t * BB + b) * CC;
    g_Axn[base + c0] = __float2half(d0 * rstd * gx[c0] + bx[c0]);
    g_Axn[base + c1] = __float2half(d1 * rstd * gx[c1] + bx[c1]);
}

// ---------------- weight conversion ----------------
__global__ void convW_proj(const float* __restrict__ Wf, const float* __restrict__ Wb) {
    int n = blockIdx.x;
    const float* src = (n < 2048) ? (Wf + (size_t)n * 512) : (Wb + (size_t)(n - 2048) * 512);
    size_t base = (size_t)n * 512;
    for (int k = threadIdx.x; k < 512; k += 256) g_Bp[base + k] = __float2half(src[k]);
}
__global__ void convW_gate(const float* __restrict__ Wg) {
    int n = blockIdx.x;
    size_t base = (size_t)n * 1024;
    for (int k = threadIdx.x; k < 1024; k += 256) g_Bg[base + k] = __float2half(Wg[base + k]);
}

// ---------------- HMMA GEMM fp16 single-pass: D = A . B^T ----------
template <int KDIM, int EPI>
__global__ void __launch_bounds__(256, 1) mm_kernel(const float* __restrict__ bias0,
                                                    const float* __restrict__ bias1) {
    __shared__ __half sA[128 * PADK];
    __shared__ __half sB[128 * PADK];

    const int tid = threadIdx.x;
    const int warp = tid >> 5, lane = tid & 31;
    const int g = lane >> 2, q = lane & 3;
    const int wm = (warp >> 1) * 32;
    const int wn = (warp & 1) * 64;
    const int m0 = blockIdx.y * 128;
    const int n0 = blockIdx.x * 128;

    const __half* A = (EPI == 0) ? g_Axn : g_AcatH;
    const __half* B = (EPI == 0) ? g_Bp : g_Bg;

    const int r0 = tid >> 2, kq0 = (tid & 3) * 8;
    const int r1 = r0 + 64;
    const __half* pA0 = A + (size_t)(m0 + r0) * KDIM + kq0;
    const __half* pA1 = A + (size_t)(m0 + r1) * KDIM + kq0;
    const __half* pB0 = B + (size_t)(n0 + r0) * KDIM + kq0;
    const __half* pB1 = B + (size_t)(n0 + r1) * KDIM + kq0;

    const int lrow = (lane & 7) + 8 * ((lane >> 3) & 1);
    const int lcol = 8 * (lane >> 4);
    const unsigned uA = s2u(sA), uB = s2u(sB);
    const unsigned offA0 = (unsigned)(((wm + lrow) * PADK + lcol) * 2);
    const unsigned offA1 = offA0 + 16 * PADK * 2;
    const unsigned offB  = (unsigned)(((wn + lrow) * PADK + lcol) * 2);

    float acc[2][8][4];
#pragma unroll
    for (int i = 0; i < 2; ++i)
#pragma unroll
        for (int j = 0; j < 8; ++j)
#pragma unroll
            for (int v = 0; v < 4; ++v) acc[i][j][v] = 0.f;

    uint4 vA0 = *(const uint4*)pA0, vA1 = *(const uint4*)pA1;
    uint4 vB0 = *(const uint4*)pB0, vB1 = *(const uint4*)pB1;

    const int NCH = KDIM / 32;
    for (int c = 0; c < NCH; ++c) {
        *(uint4*)&sA[r0 * PADK + kq0] = vA0;  *(uint4*)&sA[r1 * PADK + kq0] = vA1;
        *(uint4*)&sB[r0 * PADK + kq0] = vB0;  *(uint4*)&sB[r1 * PADK + kq0] = vB1;
        __syncthreads();

        if (c + 1 < NCH) {
            int koff = (c + 1) * 32;
            vA0 = *(const uint4*)(pA0 + koff);  vA1 = *(const uint4*)(pA1 + koff);
            vB0 = *(const uint4*)(pB0 + koff);  vB1 = *(const uint4*)(pB1 + koff);
        }

#pragma unroll
        for (int ks = 0; ks < 32; ks += 16) {
            unsigned a0[4], a1[4];
            LDSMX4(a0, uA + offA0 + ks * 2);
            LDSMX4(a1, uA + offA1 + ks * 2);
#pragma unroll
            for (int p = 0; p < 4; ++p) {
                unsigned b4[4];
                LDSMX4(b4, uB + offB + (p * 16 * PADK + ks) * 2);
#pragma unroll
                for (int e = 0; e < 2; ++e) {
                    unsigned b2[2] = {b4[e], b4[2 + e]};
                    int nt = 2 * p + e;
                    mma_f16(acc[0][nt], a0, b2);
                    mma_f16(acc[1][nt], a1, b2);
                }
            }
        }
        __syncthreads();
    }

    if (EPI == 0) {
        const bool isf = (n0 < 2048);
        float* Y = isf ? g_xg_f : g_xg_b;
        const float* bias = isf ? bias0 : bias1;
        const int nb = (n0 & 2047) + wn;
#pragma unroll
        for (int mt = 0; mt < 2; ++mt) {
            int mrow = m0 + wm + mt * 16 + g;
#pragma unroll
            for (int nt = 0; nt < 8; ++nt) {
                int ncol = nb + nt * 8 + 2 * q;
                float bx0 = bias[ncol], bx1 = bias[ncol + 1];
                float2 v0 = make_float2(acc[mt][nt][0] + bx0, acc[mt][nt][1] + bx1);
                float2 v1 = make_float2(acc[mt][nt][2] + bx0, acc[mt][nt][3] + bx1);
                *(float2*)(Y + (size_t)mrow * 2048 + ncol) = v0;
                *(float2*)(Y + (size_t)(mrow + 8) * 2048 + ncol) = v1;
            }
        }
    } else {
#pragma unroll
        for (int mt = 0; mt < 2; ++mt) {
            int mrow = m0 + wm + mt * 16 + g;
#pragma unroll
            for (int nt = 0; nt < 8; ++nt) {
                int ncol = n0 + wn + nt * 8 + 2 * q;
                float bx0 = bias0[ncol], bx1 = bias0[ncol + 1];
#pragma unroll
                for (int hh = 0; hh < 2; ++hh) {
                    int m = mrow + hh * 8;
                    float s0 = fsig(acc[mt][nt][2 * hh + 0] + bx0);
                    float s1 = fsig(acc[mt][nt][2 * hh + 1] + bx1);
                    size_t ab = (size_t)m * 1024 + ncol;
                    float2 fw = __half22float2(*(const __half2*)(g_AcatH + ab));
                    float2 bw = __half22float2(*(const __half2*)(g_AcatH + ab + 512));
                    float2 o;
                    o.x = s0 * fw.x + (1.f - s0) * bw.x;
                    o.y = s1 * fw.y + (1.f - s1) * bw.y;
                    *(float2*)(g_Hout + (size_t)m * 512 + ncol) = o;
                }
            }
        }
    }
}

// ---------------- persistent bidirectional LSTM scan (fp16 HMMA, DSMEM cluster) ----
// 128 CTAs = 8 clusters of 16. Cluster = (dir, batch-group of 16); rank = unit slice
// (32 units = 128 gate cols). h exchange via st.shared::cluster into peers' smem,
// double-buffered by step parity; one barrier.cluster per step.
__global__ void __launch_bounds__(256, 1) scan_kernel(
    const float* __restrict__ Whh_f, const float* __restrict__ bhh_f,
    const float* __restrict__ Whh_b, const float* __restrict__ bhh_b) {
    extern __shared__ char smc[];
    __half* sB = (__half*)smc;                 // [128][SPAD] Whh fp16 (static)
    __half* sH = sB + 128 * SPAD;              // [2][16][SPAD] h (parity buffers)
    float* sG   = (float*)(sH + 2 * 16 * SPAD); // [16][130]
    float* sC   = sG + 16 * 130;               // [512]
    float* sBhh = sC + 512;                    // [128]

    const int tid  = threadIdx.x;
    const int warp = tid >> 5, lane = tid & 31;
    const int g = lane >> 2, q = lane & 3;
    const int dir = blockIdx.x >> 6;
    const int grp = (blockIdx.x >> 4) & 3;
    const int j0  = (blockIdx.x & 15) * 32;    // this CTA's 32 units
    const int b0g = grp * 16;                  // batch offset
    const int wn  = warp * 16;                 // gate-col offset (8 warps x 16 = 128)

    const float* Whh = dir ? Whh_b : Whh_f;
    const float* bhh = dir ? bhh_b : bhh_f;
    const float* xg  = dir ? g_xg_b : g_xg_f;

    const unsigned uB = s2u(sB);
    const unsigned uH = s2u(sH);
    const unsigned PSTRIDE = 16 * SPAD * 2;    // parity buffer stride (bytes)

    // ---- load Whh slice [128 cols][512] fp16 ----
    {
        int row = tid >> 1;
        int k0 = (tid & 1) * 256;
        int ngl = (row >> 5) * 512 + j0 + (row & 31);
        const float* src = Whh + (size_t)ngl * 512 + k0;
#pragma unroll
        for (int k4 = 0; k4 < 256; k4 += 4) {
            float4 v = *(const float4*)(src + k4);
            sB[row * SPAD + k0 + k4 + 0] = __float2half(v.x);
            sB[row * SPAD + k0 + k4 + 1] = __float2half(v.y);
            sB[row * SPAD + k0 + k4 + 2] = __float2half(v.z);
            sB[row * SPAD + k0 + k4 + 3] = __float2half(v.w);
        }
    }
    if (tid < 128) sBhh[tid] = bhh[(tid >> 5) * 512 + j0 + (tid & 31)];
    for (int idx = tid; idx < 512; idx += 256) sC[idx] = 0.f;
    // zero parity-0 h buffer (full 16x512)
    {
        __half2 z2 = __floats2half2_rn(0.f, 0.f);
        for (int i = tid; i < 4096; i += 256) {
            int row = i >> 8, c2 = (i & 255) * 2;
            *(__half2*)&sH[row * SPAD + c2] = z2;
        }
    }
    __syncthreads();
    CLUSTER_ARRIVE();
    CLUSTER_WAIT();

    // fragment addressing (static)
    const int lrow = (lane & 7) + 8 * ((lane >> 3) & 1);
    const int lcol = 8 * (lane >> 4);
    const unsigned aA0 = uH + (unsigned)((lrow * SPAD + lcol) * 2);
    const unsigned aB  = uB + (unsigned)(((wn + lrow) * SPAD + lcol) * 2);

    // epilogue indices (static)
    const int c0a = wn + 2 * q;
    const int c0b = wn + 8 + 2 * q;
    const int ngba = (c0a >> 5) * 512 + j0 + (c0a & 31);
    const int ngbb = (c0b >> 5) * 512 + j0 + (c0b & 31);
    const int r0 = g, r1 = g + 8;
    const float2 bb0 = *(const float2*)&sBhh[c0a];
    const float2 bb1 = *(const float2*)&sBhh[c0b];

    // activation indices (static): this thread produces h for (batch ab2, units j0+au2, +1)
    const int ab2 = (tid * 2) >> 5, au2 = (tid * 2) & 31;

    // precompute remote addresses of this thread's h slot in every peer CTA (parity 0)
    unsigned rem[16];
    {
        unsigned slot0 = uH + (unsigned)((ab2 * SPAD + j0 + au2) * 2);
#pragma unroll
        for (int r = 0; r < 16; ++r) MAPA(rem[r], slot0, r);
    }

    for (int s = 0; s < TT; ++s) {
        const int t = dir ? (TT - 1 - s) : s;
        const unsigned pofs  = (unsigned)(s & 1) * PSTRIDE;       // read buffer
        const unsigned pofsN = (unsigned)((s + 1) & 1) * PSTRIDE; // write buffer

        // ---- xg prefetch (DRAM; consumed in epilogue) ----
        const float* xgt = xg + (size_t)t * BB * G4;
        float2 xv00 = __ldcg((const float2*)(xgt + (size_t)(b0g + r0) * G4 + ngba));
        float2 xv01 = __ldcg((const float2*)(xgt + (size_t)(b0g + r1) * G4 + ngba));
        float2 xv10 = __ldcg((const float2*)(xgt + (size_t)(b0g + r0) * G4 + ngbb));
        float2 xv11 = __ldcg((const float2*)(xgt + (size_t)(b0g + r1) * G4 + ngbb));

        // ---- MMA: gates[16,128] = h[16,512] . Whh_slice[128,512]^T ----
        float acc[2][4];
#pragma unroll
        for (int nt = 0; nt < 2; ++nt)
#pragma unroll
            for (int v = 0; v < 4; ++v) acc[nt][v] = 0.f;

        const unsigned aA = aA0 + pofs;
#pragma unroll
        for (int ks = 0; ks < 512; ks += 16) {
            unsigned a4[4], b4[4];
            LDSMX4(a4, aA + (unsigned)(ks * 2));
            LDSMX4(b4, aB + (unsigned)(ks * 2));
#pragma unroll
            for (int e = 0; e < 2; ++e) {
                unsigned b2[2] = {b4[e], b4[2 + e]};
                mma_f16(acc[e], a4, b2);
            }
        }

        // ---- epilogue: add xg + bhh, write gates to smem ----
        *(float2*)&sG[r0 * 130 + c0a] =
            make_float2(acc[0][0] + xv00.x + bb0.x, acc[0][1] + xv00.y + bb0.y);
        *(float2*)&sG[r1 * 130 + c0a] =
            make_float2(acc[0][2] + xv01.x + bb0.x, acc[0][3] + xv01.y + bb0.y);
        *(float2*)&sG[r0 * 130 + c0b] =
            make_float2(acc[1][0] + xv10.x + bb1.x, acc[1][1] + xv10.y + bb1.y);
        *(float2*)&sG[r1 * 130 + c0b] =
            make_float2(acc[1][2] + xv11.x + bb1.x, acc[1][3] + xv11.y + bb1.y);
        __syncthreads();

        // ---- activation + broadcast h to all cluster CTAs' sH[parity^1] ----
        {
            float2 gi = *(const float2*)&sG[ab2 * 130 + au2];
            float2 gf = *(const float2*)&sG[ab2 * 130 + 32 + au2];
            float2 gg = *(const float2*)&sG[ab2 * 130 + 64 + au2];
            float2 go = *(const float2*)&sG[ab2 * 130 + 96 + au2];
            float2 cold = *(const float2*)&sC[tid * 2];
            float cn0 = fsig(gf.x) * cold.x + fsig(gi.x) * ftanh(gg.x);
            float cn1 = fsig(gf.y) * cold.y + fsig(gi.y) * ftanh(gg.y);
            float hn0 = fsig(go.x) * ftanh(cn0);
            float hn1 = fsig(go.y) * ftanh(cn1);
            *(float2*)&sC[tid * 2] = make_float2(cn0, cn1);
            __half2 h2 = __floats2half2_rn(hn0, hn1);
            unsigned hv = *(unsigned*)&h2;
#pragma unroll
            for (int r = 0; r < 16; ++r) STSC32(rem[r] + pofsN, hv);
            int bg2 = b0g + ab2;
            size_t ar = ((size_t)bg2 * TT + t) * 1024 + (size_t)dir * 512 + j0 + au2;
            *(__half2*)&g_AcatH[ar] = h2;
        }
        // one cluster barrier per step: orders DSMEM h writes, acts as block sync too
        CLUSTER_ARRIVE();
        CLUSTER_WAIT();
    }
}

// ---------------- final layernorm -> d_out ----------------
__global__ void ln_out_kernel(const float* __restrict__ gH,
                              const float* __restrict__ bH,
                              float* __restrict__ out) {
    __shared__ float red[9];
    int r = blockIdx.x;
    const float* row = g_Hout + (size_t)r * HH;
    int c0 = threadIdx.x, c1 = threadIdx.x + 256;
    float v0 = row[c0], v1 = row[c1];
    float mean = block_reduce(v0 + v1, red) * (1.f / HH);
    float d0 = v0 - mean, d1 = v1 - mean;
    float var = block_reduce(d0 * d0 + d1 * d1, red) * (1.f / HH);
    float rstd = rsqrtf(var + 1e-5f);
    out[(size_t)r * HH + c0] = d0 * rstd * gH[c0] + bH[c0];
    out[(size_t)r * HH + c1] = d1 * rstd * gH[c1] + bH[c1];
}

// ---------------- launch ----------------
extern "C" void kernel_launch(void* const* d_in, const int* in_sizes, int n_in,
                              void* d_out, int out_size) {
    const float* x     = (const float*)d_in[0];
    const float* Wih_f = (const float*)d_in[2];
    const float* Whh_f = (const float*)d_in[3];
    const float* bih_f = (const float*)d_in[4];
    const float* bhh_f = (const float*)d_in[5];
    const float* Wih_b = (const float*)d_in[6];
    const float* Whh_b = (const float*)d_in[7];
    const float* bih_b = (const float*)d_in[8];
    const float* bhh_b = (const float*)d_in[9];
    const float* Wg    = (const float*)d_in[10];
    const float* bg    = (const float*)d_in[11];
    const float* gx    = (const float*)d_in[12];
    const float* bx    = (const float*)d_in[13];
    const float* gH    = (const float*)d_in[14];
    const float* bH    = (const float*)d_in[15];
    float* out = (float*)d_out;

    const int scan_smem = (128 * SPAD + 2 * 16 * SPAD) * 2   /* fp16 tiles */
                        + (16 * 130 + 512 + 128) * 4;        /* fp32 */
    cudaFuncSetAttribute(scan_kernel, cudaFuncAttributeMaxDynamicSharedMemorySize, scan_smem);
    cudaFuncSetAttribute(scan_kernel, cudaFuncAttributeNonPortableClusterSizeAllowed, 1);

    ln_x_kernel<<<BB * TT, 256>>>(x, gx, bx);
    convW_proj<<<4096, 256>>>(Wih_f, Wih_b);
    convW_gate<<<512, 256>>>(Wg);
    mm_kernel<512, 0><<<dim3(4096 / 128, (BB * TT) / 128), 256>>>(bih_f, bih_b);

    // cluster launch: 8 clusters x 16 CTAs
    {
        cudaLaunchConfig_t cfg = {};
        cfg.gridDim = dim3(128, 1, 1);
        cfg.blockDim = dim3(256, 1, 1);
        cfg.dynamicSmemBytes = (size_t)scan_smem;
        cfg.stream = 0;
        cudaLaunchAttribute attrs[1];
        attrs[0].id = cudaLaunchAttributeClusterDimension;
        attrs[0].val.clusterDim.x = 16;
        attrs[0].val.clusterDim.y = 1;
        attrs[0].val.clusterDim.z = 1;
        cfg.attrs = attrs;
        cfg.numAttrs = 1;
        cudaLaunchKernelEx(&cfg, scan_kernel, Whh_f, bhh_f, Whh_b, bhh_b);
    }

    mm_kernel<1024, 1><<<dim3(512 / 128, (BB * TT) / 128), 256>>>(bg, bg);
    ln_out_kernel<<<BB * TT, 256>>>(gH, bH, out);
}

// round 17
// speedup vs baseline: 1.0106x; 1.0095x over previous
#include <cuda_runtime.h>
#include <cuda_bf16.h>
#include <cuda_fp16.h>
#include <math.h>

#define BB   64
#define TT   1024
#define CC   512
#define HH   512
#define G4   2048
#define PADK 40   // padded k-stride for mm_kernel smem tiles
#define SPAD 520  // padded k-stride for scan smem tiles

// ---------------- scratch (static device memory; no allocs) ----------------
__device__ __half g_Axn[(size_t)TT * BB * CC];         // LN(x) fp16, time-major [t*B+b][C]
__device__ __half g_Bp[4096 * 512];                    // stacked Wih_f | Wih_b fp16
__device__ float g_xg_f[(size_t)TT * BB * G4];         // input projection fwd (fp32)
__device__ float g_xg_b[(size_t)TT * BB * G4];
__device__ __half g_AcatH[(size_t)BB * TT * 2 * HH];   // concat(fw,bw) fp16 [b*T+t][2H]
__device__ __half g_Bg[512 * 1024];                    // Wg fp16
__device__ float g_Hout[(size_t)BB * TT * HH];

// ---------------- fast math ----------------
__device__ __forceinline__ float ex2f(float x) { float r; asm("ex2.approx.f32 %0, %1;" : "=f"(r) : "f"(x)); return r; }
__device__ __forceinline__ float rcpf(float x) { float r; asm("rcp.approx.f32 %0, %1;" : "=f"(r) : "f"(x)); return r; }
__device__ __forceinline__ float fsig(float x) { return rcpf(1.f + ex2f(-1.4426950408889634f * x)); }
__device__ __forceinline__ float ftanh(float x) { return 1.f - 2.f * rcpf(1.f + ex2f(2.8853900817779268f * x)); }

// ---------------- mma / ldmatrix / cluster helpers ----------------
__device__ __forceinline__ void mma_f16(float* d, const unsigned* a, const unsigned* b) {
    asm volatile(
        "mma.sync.aligned.m16n8k16.row.col.f32.f16.f16.f32 "
        "{%0,%1,%2,%3}, {%4,%5,%6,%7}, {%8,%9}, {%0,%1,%2,%3};"
        : "+f"(d[0]), "+f"(d[1]), "+f"(d[2]), "+f"(d[3])
        : "r"(a[0]), "r"(a[1]), "r"(a[2]), "r"(a[3]), "r"(b[0]), "r"(b[1]));
}

#define LDSMX4(R, ADDR) \
    asm volatile("ldmatrix.sync.aligned.m8n8.x4.shared.b16 {%0,%1,%2,%3}, [%4];" \
                 : "=r"((R)[0]), "=r"((R)[1]), "=r"((R)[2]), "=r"((R)[3]) : "r"(ADDR))

#define MAPA(DST, ADDR, RANK) \
    asm volatile("mapa.shared::cluster.u32 %0, %1, %2;" : "=r"(DST) : "r"(ADDR), "r"(RANK))
#define STSC32(ADDR, VAL) \
    asm volatile("st.shared::cluster.b32 [%0], %1;" :: "r"(ADDR), "r"(VAL) : "memory")
#define CLUSTER_ARRIVE() asm volatile("barrier.cluster.arrive.aligned;" ::: "memory")
#define CLUSTER_WAIT()   asm volatile("barrier.cluster.wait.aligned;" ::: "memory")

__device__ __forceinline__ unsigned s2u(const void* p) {
    unsigned r;
    asm("{ .reg .u64 t; cvta.to.shared.u64 t, %1; cvt.u32.u64 %0, t; }" : "=r"(r) : "l"(p));
    return r;
}

// ---------------- block reduce ----------------
__device__ __forceinline__ float block_reduce(float v, float* red) {
    int lane = threadIdx.x & 31, wid = threadIdx.x >> 5;
#pragma unroll
    for (int o = 16; o > 0; o >>= 1) v += __shfl_xor_sync(0xffffffffu, v, o);
    if (lane == 0) red[wid] = v;
    __syncthreads();
    if (wid == 0) {
        float w = (lane < 8) ? red[lane] : 0.f;
#pragma unroll
        for (int o = 4; o > 0; o >>= 1) w += __shfl_xor_sync(0xffffffffu, w, o);
        if (lane == 0) red[8] = w;
    }
    __syncthreads();
    float r = red[8];
    __syncthreads();
    return r;
}

// ---------------- kernel 1: layernorm(x) -> fp16 (time-major) ----------------
__global__ void ln_x_kernel(const float* __restrict__ x,
                            const float* __restrict__ gx,
                            const float* __restrict__ bx) {
    __shared__ float red[9];
    int r = blockIdx.x;
    int b = r >> 10, t = r & 1023;
    const float* row = x + (size_t)r * CC;
    int c0 = threadIdx.x, c1 = threadIdx.x + 256;
    float v0 = row[c0], v1 = row[c1];
    float mean = block_reduce(v0 + v1, red) * (1.f / CC);
    float d0 = v0 - mean, d1 = v1 - mean;
    float var = block_reduce(d0 * d0 + d1 * d1, red) * (1.f / CC);
    float rstd = rsqrtf(var + 1e-5f);
    size_t base = ((size_t)t * BB + b) * CC;
    g_Axn[base + c0] = __float2half(d0 * rstd * gx[c0] + bx[c0]);
    g_Axn[base + c1] = __float2half(d1 * rstd * gx[c1] + bx[c1]);
}

// ---------------- weight conversion ----------------
__global__ void convW_proj(const float* __restrict__ Wf, const float* __restrict__ Wb) {
    int n = blockIdx.x;
    const float* src = (n < 2048) ? (Wf + (size_t)n * 512) : (Wb + (size_t)(n - 2048) * 512);
    size_t base = (size_t)n * 512;
    for (int k = threadIdx.x; k < 512; k += 256) g_Bp[base + k] = __float2half(src[k]);
}
__global__ void convW_gate(const float* __restrict__ Wg) {
    int n = blockIdx.x;
    size_t base = (size_t)n * 1024;
    for (int k = threadIdx.x; k < 1024; k += 256) g_Bg[base + k] = __float2half(Wg[base + k]);
}

// ---------------- HMMA GEMM fp16 single-pass: D = A . B^T ----------
template <int KDIM, int EPI>
__global__ void __launch_bounds__(256, 1) mm_kernel(const float* __restrict__ bias0,
                                                    const float* __restrict__ bias1) {
    __shared__ __half sA[128 * PADK];
    __shared__ __half sB[128 * PADK];

    const int tid = threadIdx.x;
    const int warp = tid >> 5, lane = tid & 31;
    const int g = lane >> 2, q = lane & 3;
    const int wm = (warp >> 1) * 32;
    const int wn = (warp & 1) * 64;
    const int m0 = blockIdx.y * 128;
    const int n0 = blockIdx.x * 128;

    const __half* A = (EPI == 0) ? g_Axn : g_AcatH;
    const __half* B = (EPI == 0) ? g_Bp : g_Bg;

    const int r0 = tid >> 2, kq0 = (tid & 3) * 8;
    const int r1 = r0 + 64;
    const __half* pA0 = A + (size_t)(m0 + r0) * KDIM + kq0;
    const __half* pA1 = A + (size_t)(m0 + r1) * KDIM + kq0;
    const __half* pB0 = B + (size_t)(n0 + r0) * KDIM + kq0;
    const __half* pB1 = B + (size_t)(n0 + r1) * KDIM + kq0;

    const int lrow = (lane & 7) + 8 * ((lane >> 3) & 1);
    const int lcol = 8 * (lane >> 4);
    const unsigned uA = s2u(sA), uB = s2u(sB);
    const unsigned offA0 = (unsigned)(((wm + lrow) * PADK + lcol) * 2);
    const unsigned offA1 = offA0 + 16 * PADK * 2;
    const unsigned offB  = (unsigned)(((wn + lrow) * PADK + lcol) * 2);

    float acc[2][8][4];
#pragma unroll
    for (int i = 0; i < 2; ++i)
#pragma unroll
        for (int j = 0; j < 8; ++j)
#pragma unroll
            for (int v = 0; v < 4; ++v) acc[i][j][v] = 0.f;

    uint4 vA0 = *(const uint4*)pA0, vA1 = *(const uint4*)pA1;
    uint4 vB0 = *(const uint4*)pB0, vB1 = *(const uint4*)pB1;

    const int NCH = KDIM / 32;
    for (int c = 0; c < NCH; ++c) {
        *(uint4*)&sA[r0 * PADK + kq0] = vA0;  *(uint4*)&sA[r1 * PADK + kq0] = vA1;
        *(uint4*)&sB[r0 * PADK + kq0] = vB0;  *(uint4*)&sB[r1 * PADK + kq0] = vB1;
        __syncthreads();

        if (c + 1 < NCH) {
            int koff = (c + 1) * 32;
            vA0 = *(const uint4*)(pA0 + koff);  vA1 = *(const uint4*)(pA1 + koff);
            vB0 = *(const uint4*)(pB0 + koff);  vB1 = *(const uint4*)(pB1 + koff);
        }

#pragma unroll
        for (int ks = 0; ks < 32; ks += 16) {
            unsigned a0[4], a1[4];
            LDSMX4(a0, uA + offA0 + ks * 2);
            LDSMX4(a1, uA + offA1 + ks * 2);
#pragma unroll
            for (int p = 0; p < 4; ++p) {
                unsigned b4[4];
                LDSMX4(b4, uB + offB + (p * 16 * PADK + ks) * 2);
#pragma unroll
                for (int e = 0; e < 2; ++e) {
                    unsigned b2[2] = {b4[e], b4[2 + e]};
                    int nt = 2 * p + e;
                    mma_f16(acc[0][nt], a0, b2);
                    mma_f16(acc[1][nt], a1, b2);
                }
            }
        }
        __syncthreads();
    }

    if (EPI == 0) {
        const bool isf = (n0 < 2048);
        float* Y = isf ? g_xg_f : g_xg_b;
        const float* bias = isf ? bias0 : bias1;
        const int nb = (n0 & 2047) + wn;
#pragma unroll
        for (int mt = 0; mt < 2; ++mt) {
            int mrow = m0 + wm + mt * 16 + g;
#pragma unroll
            for (int nt = 0; nt < 8; ++nt) {
                int ncol = nb + nt * 8 + 2 * q;
                float bx0 = bias[ncol], bx1 = bias[ncol + 1];
                float2 v0 = make_float2(acc[mt][nt][0] + bx0, acc[mt][nt][1] + bx1);
                float2 v1 = make_float2(acc[mt][nt][2] + bx0, acc[mt][nt][3] + bx1);
                *(float2*)(Y + (size_t)mrow * 2048 + ncol) = v0;
                *(float2*)(Y + (size_t)(mrow + 8) * 2048 + ncol) = v1;
            }
        }
    } else {
#pragma unroll
        for (int mt = 0; mt < 2; ++mt) {
            int mrow = m0 + wm + mt * 16 + g;
#pragma unroll
            for (int nt = 0; nt < 8; ++nt) {
                int ncol = n0 + wn + nt * 8 + 2 * q;
                float bx0 = bias0[ncol], bx1 = bias0[ncol + 1];
#pragma unroll
                for (int hh = 0; hh < 2; ++hh) {
                    int m = mrow + hh * 8;
                    float s0 = fsig(acc[mt][nt][2 * hh + 0] + bx0);
                    float s1 = fsig(acc[mt][nt][2 * hh + 1] + bx1);
                    size_t ab = (size_t)m * 1024 + ncol;
                    float2 fw = __half22float2(*(const __half2*)(g_AcatH + ab));
                    float2 bw = __half22float2(*(const __half2*)(g_AcatH + ab + 512));
                    float2 o;
                    o.x = s0 * fw.x + (1.f - s0) * bw.x;
                    o.y = s1 * fw.y + (1.f - s1) * bw.y;
                    *(float2*)(g_Hout + (size_t)m * 512 + ncol) = o;
                }
            }
        }
    }
}

// ---------------- persistent bidirectional LSTM scan (fp16 HMMA, DSMEM cluster) ----
// 128 CTAs = 8 clusters of 16. Cluster = (dir, batch-group of 16); rank = unit slice
// (32 units = 128 gate cols). h exchange via st.shared::cluster into peers' smem,
// double-buffered by step parity; one barrier.cluster per step.
__global__ void __launch_bounds__(256, 1) scan_kernel(
    const float* __restrict__ Whh_f, const float* __restrict__ bhh_f,
    const float* __restrict__ Whh_b, const float* __restrict__ bhh_b) {
    extern __shared__ char smc[];
    __half* sB = (__half*)smc;                 // [128][SPAD] Whh fp16 (static)
    __half* sH = sB + 128 * SPAD;              // [2][16][SPAD] h (parity buffers)
    float* sG   = (float*)(sH + 2 * 16 * SPAD); // [16][130]
    float* sC   = sG + 16 * 130;               // [512]
    float* sBhh = sC + 512;                    // [128]

    const int tid  = threadIdx.x;
    const int warp = tid >> 5, lane = tid & 31;
    const int g = lane >> 2, q = lane & 3;
    const int dir = blockIdx.x >> 6;
    const int grp = (blockIdx.x >> 4) & 3;
    const int j0  = (blockIdx.x & 15) * 32;    // this CTA's 32 units
    const int b0g = grp * 16;                  // batch offset
    const int wn  = warp * 16;                 // gate-col offset (8 warps x 16 = 128)

    const float* Whh = dir ? Whh_b : Whh_f;
    const float* bhh = dir ? bhh_b : bhh_f;
    const float* xg  = dir ? g_xg_b : g_xg_f;

    const unsigned uB = s2u(sB);
    const unsigned uH = s2u(sH);
    const unsigned PSTRIDE = 16 * SPAD * 2;    // parity buffer stride (bytes)

    // ---- load Whh slice [128 cols][512] fp16 ----
    {
        int row = tid >> 1;
        int k0 = (tid & 1) * 256;
        int ngl = (row >> 5) * 512 + j0 + (row & 31);
        const float* src = Whh + (size_t)ngl * 512 + k0;
#pragma unroll
        for (int k4 = 0; k4 < 256; k4 += 4) {
            float4 v = *(const float4*)(src + k4);
            sB[row * SPAD + k0 + k4 + 0] = __float2half(v.x);
            sB[row * SPAD + k0 + k4 + 1] = __float2half(v.y);
            sB[row * SPAD + k0 + k4 + 2] = __float2half(v.z);
            sB[row * SPAD + k0 + k4 + 3] = __float2half(v.w);
        }
    }
    if (tid < 128) sBhh[tid] = bhh[(tid >> 5) * 512 + j0 + (tid & 31)];
    for (int idx = tid; idx < 512; idx += 256) sC[idx] = 0.f;
    // zero parity-0 h buffer (full 16x512)
    {
        __half2 z2 = __floats2half2_rn(0.f, 0.f);
        for (int i = tid; i < 4096; i += 256) {
            int row = i >> 8, c2 = (i & 255) * 2;
            *(__half2*)&sH[row * SPAD + c2] = z2;
        }
    }
    __syncthreads();
    CLUSTER_ARRIVE();
    CLUSTER_WAIT();

    // fragment addressing (static)
    const int lrow = (lane & 7) + 8 * ((lane >> 3) & 1);
    const int lcol = 8 * (lane >> 4);
    const unsigned aA0 = uH + (unsigned)((lrow * SPAD + lcol) * 2);
    const unsigned aB  = uB + (unsigned)(((wn + lrow) * SPAD + lcol) * 2);

    // epilogue indices (static)
    const int c0a = wn + 2 * q;
    const int c0b = wn + 8 + 2 * q;
    const int ngba = (c0a >> 5) * 512 + j0 + (c0a & 31);
    const int ngbb = (c0b >> 5) * 512 + j0 + (c0b & 31);
    const int r0 = g, r1 = g + 8;
    const float2 bb0 = *(const float2*)&sBhh[c0a];
    const float2 bb1 = *(const float2*)&sBhh[c0b];

    // activation indices (static): this thread produces h for (batch ab2, units j0+au2, +1)
    const int ab2 = (tid * 2) >> 5, au2 = (tid * 2) & 31;

    // precompute remote addresses of this thread's h slot in every peer CTA (parity 0)
    unsigned rem[16];
    {
        unsigned slot0 = uH + (unsigned)((ab2 * SPAD + j0 + au2) * 2);
#pragma unroll
        for (int r = 0; r < 16; ++r) MAPA(rem[r], slot0, r);
    }

    for (int s = 0; s < TT; ++s) {
        const int t = dir ? (TT - 1 - s) : s;
        const unsigned pofs  = (unsigned)(s & 1) * PSTRIDE;       // read buffer
        const unsigned pofsN = (unsigned)((s + 1) & 1) * PSTRIDE; // write buffer

        // ---- xg prefetch (DRAM; consumed in epilogue) ----
        const float* xgt = xg + (size_t)t * BB * G4;
        float2 xv00 = __ldcg((const float2*)(xgt + (size_t)(b0g + r0) * G4 + ngba));
        float2 xv01 = __ldcg((const float2*)(xgt + (size_t)(b0g + r1) * G4 + ngba));
        float2 xv10 = __ldcg((const float2*)(xgt + (size_t)(b0g + r0) * G4 + ngbb));
        float2 xv11 = __ldcg((const float2*)(xgt + (size_t)(b0g + r1) * G4 + ngbb));

        // ---- MMA: gates[16,128] = h[16,512] . Whh_slice[128,512]^T ----
        float acc[2][4];
#pragma unroll
        for (int nt = 0; nt < 2; ++nt)
#pragma unroll
            for (int v = 0; v < 4; ++v) acc[nt][v] = 0.f;

        const unsigned aA = aA0 + pofs;
#pragma unroll
        for (int ks = 0; ks < 512; ks += 16) {
            unsigned a4[4], b4[4];
            LDSMX4(a4, aA + (unsigned)(ks * 2));
            LDSMX4(b4, aB + (unsigned)(ks * 2));
#pragma unroll
            for (int e = 0; e < 2; ++e) {
                unsigned b2[2] = {b4[e], b4[2 + e]};
                mma_f16(acc[e], a4, b2);
            }
        }

        // ---- epilogue: add xg + bhh, write gates to smem ----
        *(float2*)&sG[r0 * 130 + c0a] =
            make_float2(acc[0][0] + xv00.x + bb0.x, acc[0][1] + xv00.y + bb0.y);
        *(float2*)&sG[r1 * 130 + c0a] =
            make_float2(acc[0][2] + xv01.x + bb0.x, acc[0][3] + xv01.y + bb0.y);
        *(float2*)&sG[r0 * 130 + c0b] =
            make_float2(acc[1][0] + xv10.x + bb1.x, acc[1][1] + xv10.y + bb1.y);
        *(float2*)&sG[r1 * 130 + c0b] =
            make_float2(acc[1][2] + xv11.x + bb1.x, acc[1][3] + xv11.y + bb1.y);
        __syncthreads();

        // ---- activation + broadcast h to all cluster CTAs' sH[parity^1] ----
        {
            float2 gi = *(const float2*)&sG[ab2 * 130 + au2];
            float2 gf = *(const float2*)&sG[ab2 * 130 + 32 + au2];
            float2 gg = *(const float2*)&sG[ab2 * 130 + 64 + au2];
            float2 go = *(const float2*)&sG[ab2 * 130 + 96 + au2];
            float2 cold = *(const float2*)&sC[tid * 2];
            float cn0 = fsig(gf.x) * cold.x + fsig(gi.x) * ftanh(gg.x);
            float cn1 = fsig(gf.y) * cold.y + fsig(gi.y) * ftanh(gg.y);
            float hn0 = fsig(go.x) * ftanh(cn0);
            float hn1 = fsig(go.y) * ftanh(cn1);
            *(float2*)&sC[tid * 2] = make_float2(cn0, cn1);
            __half2 h2 = __floats2half2_rn(hn0, hn1);
            unsigned hv = *(unsigned*)&h2;
#pragma unroll
            for (int r = 0; r < 16; ++r) STSC32(rem[r] + pofsN, hv);
            int bg2 = b0g + ab2;
            size_t ar = ((size_t)bg2 * TT + t) * 1024 + (size_t)dir * 512 + j0 + au2;
            *(__half2*)&g_AcatH[ar] = h2;
        }
        // one cluster barrier per step: orders DSMEM h writes, acts as block sync too
        CLUSTER_ARRIVE();
        CLUSTER_WAIT();
    }
}

// ---------------- final layernorm -> d_out ----------------
__global__ void ln_out_kernel(const float* __restrict__ gH,
                              const float* __restrict__ bH,
                              float* __restrict__ out) {
    __shared__ float red[9];
    int r = blockIdx.x;
    const float* row = g_Hout + (size_t)r * HH;
    int c0 = threadIdx.x, c1 = threadIdx.x + 256;
    float v0 = row[c0], v1 = row[c1];
    float mean = block_reduce(v0 + v1, red) * (1.f / HH);
    float d0 = v0 - mean, d1 = v1 - mean;
    float var = block_reduce(d0 * d0 + d1 * d1, red) * (1.f / HH);
    float rstd = rsqrtf(var + 1e-5f);
    out[(size_t)r * HH + c0] = d0 * rstd * gH[c0] + bH[c0];
    out[(size_t)r * HH + c1] = d1 * rstd * gH[c1] + bH[c1];
}

// ---------------- launch ----------------
extern "C" void kernel_launch(void* const* d_in, const int* in_sizes, int n_in,
                              void* d_out, int out_size) {
    const float* x     = (const float*)d_in[0];
    const float* Wih_f = (const float*)d_in[2];
    const float* Whh_f = (const float*)d_in[3];
    const float* bih_f = (const float*)d_in[4];
    const float* bhh_f = (const float*)d_in[5];
    const float* Wih_b = (const float*)d_in[6];
    const float* Whh_b = (const float*)d_in[7];
    const float* bih_b = (const float*)d_in[8];
    const float* bhh_b = (const float*)d_in[9];
    const float* Wg    = (const float*)d_in[10];
    const float* bg    = (const float*)d_in[11];
    const float* gx    = (const float*)d_in[12];
    const float* bx    = (const float*)d_in[13];
    const float* gH    = (const float*)d_in[14];
    const float* bH    = (const float*)d_in[15];
    float* out = (float*)d_out;

    const int scan_smem = (128 * SPAD + 2 * 16 * SPAD) * 2   /* fp16 tiles */
                        + (16 * 130 + 512 + 128) * 4;        /* fp32 */
    cudaFuncSetAttribute(scan_kernel, cudaFuncAttributeMaxDynamicSharedMemorySize, scan_smem);
    cudaFuncSetAttribute(scan_kernel, cudaFuncAttributeNonPortableClusterSizeAllowed, 1);

    ln_x_kernel<<<BB * TT, 256>>>(x, gx, bx);
    convW_proj<<<4096, 256>>>(Wih_f, Wih_b);
    convW_gate<<<512, 256>>>(Wg);
    mm_kernel<512, 0><<<dim3(4096 / 128, (BB * TT) / 128), 256>>>(bih_f, bih_b);

    // cluster launch: 8 clusters x 16 CTAs
    {
        cudaLaunchConfig_t cfg = {};
        cfg.gridDim = dim3(128, 1, 1);
        cfg.blockDim = dim3(256, 1, 1);
        cfg.dynamicSmemBytes = (size_t)scan_smem;
        cfg.stream = 0;
        cudaLaunchAttribute attrs[1];
        attrs[0].id = cudaLaunchAttributeClusterDimension;
        attrs[0].val.clusterDim.x = 16;
        attrs[0].val.clusterDim.y = 1;
        attrs[0].val.clusterDim.z = 1;
        cfg.attrs = attrs;
        cfg.numAttrs = 1;
        cudaLaunchKernelEx(&cfg, scan_kernel, Whh_f, bhh_f, Whh_b, bhh_b);
    }

    mm_kernel<1024, 1><<<dim3(512 / 128, (BB * TT) / 128), 256>>>(bg, bg);
    ln_out_kernel<<<BB * TT, 256>>>(gH, bH, out);
}